// round 3
// baseline (speedup 1.0000x reference)
#include <cuda_runtime.h>
#include <math.h>

// Problem constants
#define BB 2048
#define SS 24
#define TT 25
#define HH 256
#define EE 300
#define VIN 64
#define VOUT 128
#define G3 768   // 3*H

// ---------------- scratch (device globals; no allocation) ----------------
__device__ float g_encInF[VIN * G3];
__device__ float g_encInB[VIN * G3];
__device__ float g_decEmbW[VOUT * G3];
__device__ float g_decEmbFc[VOUT * VOUT];
__device__ float g_hFa[BB * HH];
__device__ float g_hFb[BB * HH];
__device__ float g_hBa[BB * HH];
__device__ float g_hBb[BB * HH];
__device__ float g_gh1[BB * G3];
__device__ float g_gh2[BB * G3];
__device__ float g_encBse[BB * SS * 2 * HH];   // (B, S, 512)
__device__ float g_encProj[BB * SS * HH];      // (B, S, 256)
__device__ float g_hcat[BB * 2 * HH];
__device__ float g_dhA[BB * HH];
__device__ float g_dhB[BB * HH];
__device__ float g_hWh[BB * HH];
__device__ float g_weighted[BB * 2 * HH];
__device__ float g_giDec[BB * G3];
__device__ float g_cat768[BB * G3];

// ---------------- small kernels ----------------
__global__ void zero_kernel(float* p, int n) {
    int i = blockIdx.x * blockDim.x + threadIdx.x;
    if (i < n) p[i] = 0.0f;
}

// out[v][n] = sum_e emb[v][e] * W[e][n] + bias[n]   (tiny GEMMs, naive)
__global__ void table_kernel(const float* __restrict__ emb, int Edim,
                             const float* __restrict__ W,
                             const float* __restrict__ bias,
                             float* __restrict__ out, int V, int N) {
    int t = blockIdx.x * blockDim.x + threadIdx.x;
    if (t >= V * N) return;
    int v = t / N, n = t % N;
    float acc = bias ? bias[n] : 0.0f;
    const float* er = emb + v * Edim;
    for (int e = 0; e < Edim; e++) acc += er[e] * W[e * N + n];
    out[t] = acc;
}

// dst[b][0:na]=a[b], dst[b][na:na+nb]=b2[b]
__global__ void concat2_kernel(const float* __restrict__ a, int na,
                               const float* __restrict__ b2, int nb,
                               float* __restrict__ dst, int rows) {
    int w = na + nb;
    int t = blockIdx.x * blockDim.x + threadIdx.x;
    if (t >= rows * w) return;
    int r = t / w, c = t % w;
    dst[t] = (c < na) ? a[r * na + c] : b2[r * nb + (c - na)];
}

// ---------------- tiled SGEMM: C = A(MxK) @ B(KxN) [+bias] [+gather-table row] [tanh] ----------------
// 64x64 tile, BK=16, 256 threads, 4x4 per thread. All dims divisible by tile sizes.
__global__ __launch_bounds__(256) void sgemm_kernel(
    const float* __restrict__ A, int lda,
    const float* __restrict__ Bm, int ldb,
    float* __restrict__ C, int ldc,
    int M, int N, int K,
    const float* __restrict__ bias,
    const float* __restrict__ gtab, const int* __restrict__ gidx, int gld,
    int act) {
    __shared__ float As[16][64];
    __shared__ float Bs[16][64];
    int tid = threadIdx.x;
    int tx = tid & 15, ty = tid >> 4;
    int row0 = blockIdx.y * 64, col0 = blockIdx.x * 64;
    float acc[4][4] = {};

    for (int k0 = 0; k0 < K; k0 += 16) {
        #pragma unroll
        for (int p = 0; p < 4; p++) {
            int e = tid + p * 256;
            int m = e >> 4, k = e & 15;
            As[k][m] = A[(row0 + m) * lda + k0 + k];
        }
        #pragma unroll
        for (int p = 0; p < 4; p++) {
            int e = tid + p * 256;
            int k = e >> 6, n = e & 63;
            Bs[k][n] = Bm[(k0 + k) * ldb + col0 + n];
        }
        __syncthreads();
        #pragma unroll
        for (int kk = 0; kk < 16; kk++) {
            float4 av = *reinterpret_cast<const float4*>(&As[kk][ty * 4]);
            float4 bv = *reinterpret_cast<const float4*>(&Bs[kk][tx * 4]);
            float a4[4] = {av.x, av.y, av.z, av.w};
            float b4[4] = {bv.x, bv.y, bv.z, bv.w};
            #pragma unroll
            for (int i = 0; i < 4; i++)
                #pragma unroll
                for (int j = 0; j < 4; j++)
                    acc[i][j] += a4[i] * b4[j];
        }
        __syncthreads();
    }

    #pragma unroll
    for (int i = 0; i < 4; i++) {
        int m = row0 + ty * 4 + i;
        const float* grow = gtab ? (gtab + gidx[m] * gld) : nullptr;
        #pragma unroll
        for (int j = 0; j < 4; j++) {
            int n = col0 + tx * 4 + j;
            float v = acc[i][j];
            if (bias) v += bias[n];
            if (grow) v += grow[n];
            if (act) v = tanhf(v);
            C[m * ldc + n] = v;
        }
    }
}

// ---------------- GRU gate kernel ----------------
// gi row from gather table (giTab[idx[b]]) or from buffer gi[b]. One thread per (b,j).
__global__ void gru_gate_kernel(const float* __restrict__ giTab,
                                const int* __restrict__ idx,
                                const float* __restrict__ gi,
                                const float* __restrict__ gh,
                                const float* __restrict__ hprev,
                                float* __restrict__ hout,
                                float* __restrict__ seqdst, int seqStride) {
    int t = blockIdx.x * blockDim.x + threadIdx.x;
    int b = t >> 8;
    int j = t & 255;
    const float* g = idx ? (giTab + idx[b] * G3) : (gi + b * G3);
    float gr = g[j], gz = g[j + HH], gn = g[j + 2 * HH];
    const float* G = gh + b * G3;
    float hr = G[j], hz = G[j + HH], hn2 = G[j + 2 * HH];
    float r = 1.0f / (1.0f + expf(-(gr + hr)));
    float z = 1.0f / (1.0f + expf(-(gz + hz)));
    float n = tanhf(gn + r * hn2);
    float hp = hprev[b * HH + j];
    float hv = (1.0f - z) * n + z * hp;
    hout[b * HH + j] = hv;
    if (seqdst) seqdst[b * seqStride + j] = hv;
}

// ---------------- fused attention kernel (one block per batch element) ----------------
__global__ __launch_bounds__(256) void attn_kernel(
    const float* __restrict__ hWh,     // B x 256
    const float* __restrict__ proj,    // B x S x 256
    const float* __restrict__ encBse,  // B x S x 512
    const float* __restrict__ attn_b,  // 256
    const float* __restrict__ attn_v,  // 256
    float* __restrict__ weighted) {    // B x 512
    int b = blockIdx.x;
    int tid = threadIdx.x;
    __shared__ float hb[256];
    __shared__ float vsh[256];
    __shared__ float sc[SS];
    __shared__ float a_sm[SS];
    hb[tid] = hWh[b * 256 + tid] + attn_b[tid];
    vsh[tid] = attn_v[tid];
    __syncthreads();
    int warp = tid >> 5, lane = tid & 31;
    for (int s = warp; s < SS; s += 8) {
        const float* pr = proj + (b * SS + s) * 256;
        float sum = 0.0f;
        #pragma unroll
        for (int i = 0; i < 8; i++) {
            int k = lane + i * 32;
            sum += tanhf(hb[k] + pr[k]) * vsh[k];
        }
        #pragma unroll
        for (int o = 16; o > 0; o >>= 1) sum += __shfl_xor_sync(0xFFFFFFFFu, sum, o);
        if (lane == 0) sc[s] = sum;
    }
    __syncthreads();
    if (warp == 0) {
        float v = (lane < SS) ? sc[lane] : -1e30f;
        float mx = v;
        #pragma unroll
        for (int o = 16; o > 0; o >>= 1) mx = fmaxf(mx, __shfl_xor_sync(0xFFFFFFFFu, mx, o));
        float e = (lane < SS) ? expf(v - mx) : 0.0f;
        float ssum = e;
        #pragma unroll
        for (int o = 16; o > 0; o >>= 1) ssum += __shfl_xor_sync(0xFFFFFFFFu, ssum, o);
        if (lane < SS) a_sm[lane] = e / ssum;
    }
    __syncthreads();
    #pragma unroll
    for (int it = 0; it < 2; it++) {
        int d = tid + it * 256;
        const float* eb = encBse + b * SS * 512 + d;
        float acc = 0.0f;
        #pragma unroll
        for (int s = 0; s < SS; s++) acc += a_sm[s] * eb[s * 512];
        weighted[b * 512 + d] = acc;
    }
}

// ---------------- host side ----------------
static inline float* symf(const void* s) {
    void* p = nullptr;
    cudaGetSymbolAddress(&p, s);
    return (float*)p;
}

static void sgemm(const float* A, int lda, const float* Bm, int ldb,
                  float* C, int ldc, int M, int N, int K,
                  const float* bias, const float* gtab, const int* gidx, int gld, int act) {
    dim3 grid(N / 64, M / 64);
    sgemm_kernel<<<grid, 256>>>(A, lda, Bm, ldb, C, ldc, M, N, K, bias, gtab, gidx, gld, act);
}

extern "C" void kernel_launch(void* const* d_in, const int* in_sizes, int n_in,
                              void* d_out, int out_size) {
    const int*   src       = (const int*)  d_in[0];
    const int*   trg       = (const int*)  d_in[1];
    const float* enc_emb   = (const float*)d_in[2];
    const float* enc_Wih_f = (const float*)d_in[3];
    const float* enc_Whh_f = (const float*)d_in[4];
    const float* enc_bih_f = (const float*)d_in[5];
    const float* enc_bhh_f = (const float*)d_in[6];
    const float* enc_Wih_b = (const float*)d_in[7];
    const float* enc_Whh_b = (const float*)d_in[8];
    const float* enc_bih_b = (const float*)d_in[9];
    const float* enc_bhh_b = (const float*)d_in[10];
    const float* enc_fcW   = (const float*)d_in[11];
    const float* enc_fcb   = (const float*)d_in[12];
    const float* attn_Wh   = (const float*)d_in[13];
    const float* attn_We   = (const float*)d_in[14];
    const float* attn_b    = (const float*)d_in[15];
    const float* attn_v    = (const float*)d_in[16];
    const float* dec_emb   = (const float*)d_in[17];
    const float* dec_Wih   = (const float*)d_in[18];
    const float* dec_Whh   = (const float*)d_in[19];
    const float* dec_bih   = (const float*)d_in[20];
    const float* dec_bhh   = (const float*)d_in[21];
    const float* fcW       = (const float*)d_in[22];
    const float* fcb       = (const float*)d_in[23];
    float* out = (float*)d_out;

    float* encInF   = symf(g_encInF);
    float* encInB   = symf(g_encInB);
    float* decEmbW  = symf(g_decEmbW);
    float* decEmbFc = symf(g_decEmbFc);
    float* hFa = symf(g_hFa); float* hFb = symf(g_hFb);
    float* hBa = symf(g_hBa); float* hBb = symf(g_hBb);
    float* gh1 = symf(g_gh1); float* gh2 = symf(g_gh2);
    float* encBse  = symf(g_encBse);
    float* encProj = symf(g_encProj);
    float* hcat    = symf(g_hcat);
    float* dhA = symf(g_dhA); float* dhB = symf(g_dhB);
    float* hWh = symf(g_hWh);
    float* weighted = symf(g_weighted);
    float* giDec = symf(g_giDec);
    float* cat768 = symf(g_cat768);

    // zero initial hidden states and output slice 0
    zero_kernel<<<(BB * HH + 255) / 256, 256>>>(hFa, BB * HH);
    zero_kernel<<<(BB * HH + 255) / 256, 256>>>(hBa, BB * HH);
    zero_kernel<<<(BB * VOUT + 255) / 256, 256>>>(out, BB * VOUT);

    // precompute embedding-times-weight tables
    table_kernel<<<(VIN * G3 + 255) / 256, 256>>>(enc_emb, EE, enc_Wih_f, enc_bih_f, encInF, VIN, G3);
    table_kernel<<<(VIN * G3 + 255) / 256, 256>>>(enc_emb, EE, enc_Wih_b, enc_bih_b, encInB, VIN, G3);
    table_kernel<<<(VOUT * G3 + 255) / 256, 256>>>(dec_emb, EE, dec_Wih, dec_bih, decEmbW, VOUT, G3);
    table_kernel<<<(VOUT * VOUT + 255) / 256, 256>>>(dec_emb, EE, fcW + 768 * VOUT, fcb, decEmbFc, VOUT, VOUT);

    // ---------------- encoder: bidirectional GRU ----------------
    float* hf_in = hFa; float* hf_out = hFb;
    float* hb_in = hBa; float* hb_out = hBb;
    for (int s = 0; s < SS; s++) {
        // forward direction, step s
        sgemm(hf_in, HH, enc_Whh_f, G3, gh1, G3, BB, G3, HH, enc_bhh_f, nullptr, nullptr, 0, 0);
        gru_gate_kernel<<<BB, 256>>>(encInF, src + s * BB, nullptr, gh1, hf_in, hf_out,
                                     encBse + s * 512, SS * 512);
        // backward direction, processes x[S-1-s], writes slot S-1-s cols [256:512)
        sgemm(hb_in, HH, enc_Whh_b, G3, gh2, G3, BB, G3, HH, enc_bhh_b, nullptr, nullptr, 0, 0);
        gru_gate_kernel<<<BB, 256>>>(encInB, src + (SS - 1 - s) * BB, nullptr, gh2, hb_in, hb_out,
                                     encBse + (SS - 1 - s) * 512 + 256, SS * 512);
        { float* t0 = hf_in; hf_in = hf_out; hf_out = t0; }
        { float* t1 = hb_in; hb_in = hb_out; hb_out = t1; }
    }
    // hidden = tanh([hf, hb] @ enc_fcW + enc_fcb)
    concat2_kernel<<<(BB * 512 + 255) / 256, 256>>>(hf_in, HH, hb_in, HH, hcat, BB);
    sgemm(hcat, 512, enc_fcW, HH, dhA, HH, BB, HH, 512, enc_fcb, nullptr, nullptr, 0, 1);

    // enc_proj = enc_bse @ attn_We : (B*S, 512) x (512, 256)
    sgemm(encBse, 512, attn_We, HH, encProj, HH, BB * SS, HH, 512, nullptr, nullptr, nullptr, 0, 0);

    // ---------------- decoder ----------------
    float* h_in = dhA; float* h_out = dhB;
    for (int t = 0; t < TT - 1; t++) {
        const int* idx = trg + t * BB;
        // attention
        sgemm(h_in, HH, attn_Wh, HH, hWh, HH, BB, HH, HH, nullptr, nullptr, nullptr, 0, 0);
        attn_kernel<<<BB, 256>>>(hWh, encProj, encBse, attn_b, attn_v, weighted);
        // gi = weighted @ dec_Wih[300:812] + decEmbW[trg[t]]  (includes dec_bih)
        sgemm(weighted, 512, dec_Wih + EE * G3, G3, giDec, G3, BB, G3, 512,
              nullptr, decEmbW, idx, G3, 0);
        // gh = h @ dec_Whh + dec_bhh
        sgemm(h_in, HH, dec_Whh, G3, gh1, G3, BB, G3, HH, dec_bhh, nullptr, nullptr, 0, 0);
        // gates
        gru_gate_kernel<<<BB, 256>>>(nullptr, nullptr, giDec, gh1, h_in, h_out, nullptr, 0);
        // logits = [hn, weighted] @ fcW[0:768] + decEmbFc[trg[t]]  (includes fcb)
        concat2_kernel<<<(BB * G3 + 255) / 256, 256>>>(h_out, HH, weighted, 512, cat768, BB);
        sgemm(cat768, G3, fcW, VOUT, out + (size_t)(t + 1) * BB * VOUT, VOUT, BB, VOUT, G3,
              nullptr, decEmbFc, idx, VOUT, 0);
        { float* t2 = h_in; h_in = h_out; h_out = t2; }
    }
}

// round 5
// speedup vs baseline: 1.8325x; 1.8325x over previous
#include <cuda_runtime.h>
#include <math.h>

// Problem constants
#define BB 2048
#define SS 24
#define TT 25
#define HH 256
#define EE 300
#define VIN 64
#define VOUT 128
#define G3 768   // 3*H

// ---------------- scratch (device globals; no allocation) ----------------
__device__ float g_encInF[VIN * G3];
__device__ float g_encInB[VIN * G3];
__device__ float g_decEmbW[VOUT * G3];
__device__ float g_decEmbFc[VOUT * VOUT];
__device__ float g_hFa[BB * HH];
__device__ float g_hFb[BB * HH];
__device__ float g_hBa[BB * HH];
__device__ float g_hBb[BB * HH];
__device__ float g_gh1[BB * G3];
__device__ float g_gh2[BB * G3];
__device__ float g_encBse[BB * SS * 2 * HH];   // (B, S, 512)
__device__ float g_encProj[BB * SS * HH];      // (B, S, 256)
__device__ float g_hcat[BB * 2 * HH];
__device__ float g_dhA[BB * HH];
__device__ float g_dhB[BB * HH];
__device__ float g_hWhGh[BB * 1024];           // [hWh(256) | gh(768)] per row
__device__ float g_Wcomb[HH * 1024];           // [attn_Wh | dec_Whh]
__device__ float g_bcomb[1024];                // [0 | dec_bhh]
__device__ float g_catAll[(TT - 1) * BB * G3]; // per-step [h(256) | weighted(512)]

// ---------------- small kernels ----------------
__global__ void zero_kernel(float* p, int n) {
    int i = blockIdx.x * blockDim.x + threadIdx.x;
    if (i < n) p[i] = 0.0f;
}

// out[v][n] = sum_e emb[v][e] * W[e][n] + bias[n]
__global__ void table_kernel(const float* __restrict__ emb, int Edim,
                             const float* __restrict__ W,
                             const float* __restrict__ bias,
                             float* __restrict__ out, int V, int N) {
    int t = blockIdx.x * blockDim.x + threadIdx.x;
    if (t >= V * N) return;
    int v = t / N, n = t % N;
    float acc = bias ? bias[n] : 0.0f;
    const float* er = emb + v * Edim;
    #pragma unroll 4
    for (int e = 0; e < Edim; e++) acc += er[e] * W[e * N + n];
    out[t] = acc;
}

__global__ void concat2_kernel(const float* __restrict__ a, int na,
                               const float* __restrict__ b2, int nb,
                               float* __restrict__ dst, int rows) {
    int w = na + nb;
    int t = blockIdx.x * blockDim.x + threadIdx.x;
    if (t >= rows * w) return;
    int r = t / w, c = t % w;
    dst[t] = (c < na) ? a[r * na + c] : b2[r * nb + (c - na)];
}

// Build combined decoder weight/bias: W(256x1024) = [attn_Wh | dec_Whh], b = [0 | dec_bhh]
__global__ void build_comb_kernel(const float* __restrict__ attn_Wh,
                                  const float* __restrict__ dec_Whh,
                                  const float* __restrict__ dec_bhh,
                                  float* __restrict__ W, float* __restrict__ bias) {
    int t = blockIdx.x * blockDim.x + threadIdx.x;
    if (t >= HH * 1024) return;
    int r = t >> 10, c = t & 1023;
    W[t] = (c < HH) ? attn_Wh[r * HH + c] : dec_Whh[r * G3 + (c - HH)];
    if (r == 0) bias[c] = (c < HH) ? 0.0f : dec_bhh[c - HH];
}

// ---------------- 128x64 tiled SGEMM, BK=16, 256 threads, 8x4 per thread ----------------
// Optional 2-way batch via blockIdx.z. Optional bias, gather-table row add, tanh.
__global__ __launch_bounds__(256) void sgemm128_kernel(
    const float* __restrict__ A0, const float* __restrict__ A1, int lda,
    const float* __restrict__ B0, const float* __restrict__ B1, int ldb,
    float* __restrict__ C0, float* __restrict__ C1, int ldc,
    int K,
    const float* __restrict__ bias0, const float* __restrict__ bias1,
    const float* __restrict__ gtab, const int* __restrict__ gidx, int gld,
    int act) {
    const float* A = blockIdx.z ? A1 : A0;
    const float* Bm = blockIdx.z ? B1 : B0;
    float* C = blockIdx.z ? C1 : C0;
    const float* bias = blockIdx.z ? bias1 : bias0;

    __shared__ float As[16 * 132];   // padded stride 132 (float4-aligned, conflict-light)
    __shared__ float Bs[16 * 64];

    int tid = threadIdx.x;
    int tx = tid & 15;          // 0..15 -> 4 cols each
    int ty = tid >> 4;          // 0..15 -> 8 rows each
    int row0 = blockIdx.y * 128, col0 = blockIdx.x * 64;
    float acc[8][4] = {};

    for (int k0 = 0; k0 < K; k0 += 16) {
        // A tile: 128 rows x 16 k, transposed into As[k][m]
        #pragma unroll
        for (int p = 0; p < 2; p++) {
            int q = tid + p * 256;           // 0..511
            int row = q >> 2;                // 0..127
            int kq = (q & 3) * 4;            // 0,4,8,12
            float4 v = *reinterpret_cast<const float4*>(
                &A[(size_t)(row0 + row) * lda + k0 + kq]);
            As[(kq + 0) * 132 + row] = v.x;
            As[(kq + 1) * 132 + row] = v.y;
            As[(kq + 2) * 132 + row] = v.z;
            As[(kq + 3) * 132 + row] = v.w;
        }
        // B tile: 16 k x 64 cols
        {
            int q = tid;                     // 0..255
            int k = q >> 4;                  // 0..15
            int n = (q & 15) * 4;            // 0..60
            float4 v = *reinterpret_cast<const float4*>(
                &Bm[(size_t)(k0 + k) * ldb + col0 + n]);
            *reinterpret_cast<float4*>(&Bs[k * 64 + n]) = v;
        }
        __syncthreads();
        #pragma unroll
        for (int kk = 0; kk < 16; kk++) {
            float4 b4 = *reinterpret_cast<const float4*>(&Bs[kk * 64 + tx * 4]);
            float4 a0 = *reinterpret_cast<const float4*>(&As[kk * 132 + ty * 8]);
            float4 a1 = *reinterpret_cast<const float4*>(&As[kk * 132 + ty * 8 + 4]);
            float a[8] = {a0.x, a0.y, a0.z, a0.w, a1.x, a1.y, a1.z, a1.w};
            float b[4] = {b4.x, b4.y, b4.z, b4.w};
            #pragma unroll
            for (int i = 0; i < 8; i++)
                #pragma unroll
                for (int j = 0; j < 4; j++)
                    acc[i][j] += a[i] * b[j];
        }
        __syncthreads();
    }

    #pragma unroll
    for (int i = 0; i < 8; i++) {
        int m = row0 + ty * 8 + i;
        const float* grow = gtab ? (gtab + (size_t)gidx[m] * gld) : nullptr;
        int n0 = col0 + tx * 4;
        float o[4];
        #pragma unroll
        for (int j = 0; j < 4; j++) {
            float v = acc[i][j];
            if (bias) v += bias[n0 + j];
            if (grow) v += grow[n0 + j];
            if (act) v = tanhf(v);
            o[j] = v;
        }
        *reinterpret_cast<float4*>(&C[(size_t)m * ldc + n0]) =
            make_float4(o[0], o[1], o[2], o[3]);
    }
}

// ---------------- GRU gate kernels ----------------
// Decoder: gi from buffer (lda G3), gh from hWhGh+256 with ld 1024.
__global__ void gru_gate_kernel(const float* __restrict__ gi, int gild,
                                const float* __restrict__ gh, int ghld,
                                const float* __restrict__ hprev,
                                float* __restrict__ hout,
                                float* __restrict__ seqdst, int seqStride) {
    int t = blockIdx.x * blockDim.x + threadIdx.x;
    int b = t >> 8;
    int j = t & 255;
    const float* g = gi + (size_t)b * gild;
    const float* G = gh + (size_t)b * ghld;
    float gr = g[j], gz = g[j + HH], gn = g[j + 2 * HH];
    float hr = G[j], hz = G[j + HH], hn2 = G[j + 2 * HH];
    float r = 1.0f / (1.0f + __expf(-(gr + hr)));
    float z = 1.0f / (1.0f + __expf(-(gz + hz)));
    float n = tanhf(gn + r * hn2);
    float hp = hprev[b * HH + j];
    float hv = (1.0f - z) * n + z * hp;
    hout[b * HH + j] = hv;
    if (seqdst) seqdst[(size_t)b * seqStride + j] = hv;
}

// Encoder: both directions fused. grid = 2*BB blocks of 256.
__global__ void enc_gate_kernel(const float* __restrict__ giTabF,
                                const float* __restrict__ giTabB,
                                const int* __restrict__ src, int s,
                                const float* __restrict__ ghF,
                                const float* __restrict__ ghB,
                                const float* __restrict__ hprevF,
                                const float* __restrict__ hprevB,
                                float* __restrict__ houtF,
                                float* __restrict__ houtB,
                                float* __restrict__ encBse) {
    int dir = blockIdx.x >> 11;
    int b = blockIdx.x & (BB - 1);
    int j = threadIdx.x;
    int step = dir ? (SS - 1 - s) : s;
    int tok = src[step * BB + b];
    const float* g = (dir ? giTabB : giTabF) + (size_t)tok * G3;
    const float* G = (dir ? ghB : ghF) + (size_t)b * G3;
    float r = 1.0f / (1.0f + __expf(-(g[j] + G[j])));
    float z = 1.0f / (1.0f + __expf(-(g[j + HH] + G[j + HH])));
    float n = tanhf(g[j + 2 * HH] + r * G[j + 2 * HH]);
    const float* hp = (dir ? hprevB : hprevF) + b * HH;
    float hv = (1.0f - z) * n + z * hp[j];
    (dir ? houtB : houtF)[b * HH + j] = hv;
    encBse[((size_t)b * SS + step) * 512 + dir * 256 + j] = hv;
}

// ---------------- fused attention kernel (one block per batch element) ----------------
// Reads hWh from hWhGh (ld 1024). Writes weighted into catAll slot cols [256:768).
__global__ __launch_bounds__(256) void attn_kernel(
    const float* __restrict__ hWhGh,   // B x 1024 (first 256 = hWh)
    const float* __restrict__ proj,    // B x S x 256
    const float* __restrict__ encBse,  // B x S x 512
    const float* __restrict__ attn_b,  // 256
    const float* __restrict__ attn_v,  // 256
    float* __restrict__ catw) {        // (B x 768) slot base for this step
    int b = blockIdx.x;
    int tid = threadIdx.x;
    __shared__ float hb[256];
    __shared__ float vsh[256];
    __shared__ float sc[SS];
    __shared__ float a_sm[SS];
    hb[tid] = hWhGh[b * 1024 + tid] + attn_b[tid];
    vsh[tid] = attn_v[tid];
    __syncthreads();
    int warp = tid >> 5, lane = tid & 31;
    for (int s = warp; s < SS; s += 8) {
        const float* pr = proj + ((size_t)b * SS + s) * 256;
        float sum = 0.0f;
        #pragma unroll
        for (int i = 0; i < 8; i++) {
            int k = lane + i * 32;
            sum += tanhf(hb[k] + pr[k]) * vsh[k];
        }
        #pragma unroll
        for (int o = 16; o > 0; o >>= 1) sum += __shfl_xor_sync(0xFFFFFFFFu, sum, o);
        if (lane == 0) sc[s] = sum;
    }
    __syncthreads();
    if (warp == 0) {
        float v = (lane < SS) ? sc[lane] : -1e30f;
        float mx = v;
        #pragma unroll
        for (int o = 16; o > 0; o >>= 1) mx = fmaxf(mx, __shfl_xor_sync(0xFFFFFFFFu, mx, o));
        float e = (lane < SS) ? __expf(v - mx) : 0.0f;
        float ssum = e;
        #pragma unroll
        for (int o = 16; o > 0; o >>= 1) ssum += __shfl_xor_sync(0xFFFFFFFFu, ssum, o);
        if (lane < SS) a_sm[lane] = e / ssum;
    }
    __syncthreads();
    #pragma unroll
    for (int it = 0; it < 2; it++) {
        int d = tid + it * 256;
        const float* eb = encBse + (size_t)b * SS * 512 + d;
        float acc = 0.0f;
        #pragma unroll
        for (int s = 0; s < SS; s++) acc += a_sm[s] * eb[s * 512];
        catw[(size_t)b * G3 + 256 + d] = acc;
    }
}

// ---------------- host side ----------------
static inline float* symf(const void* s) {
    void* p = nullptr;
    cudaGetSymbolAddress(&p, s);
    return (float*)p;
}

static void sgemm(const float* A, int lda, const float* Bm, int ldb,
                  float* C, int ldc, int M, int N, int K,
                  const float* bias, const float* gtab, const int* gidx, int gld, int act) {
    dim3 grid(N / 64, M / 128, 1);
    sgemm128_kernel<<<grid, 256>>>(A, nullptr, lda, Bm, nullptr, ldb, C, nullptr, ldc,
                                   K, bias, nullptr, gtab, gidx, gld, act);
}

extern "C" void kernel_launch(void* const* d_in, const int* in_sizes, int n_in,
                              void* d_out, int out_size) {
    const int*   src       = (const int*)  d_in[0];
    const int*   trg       = (const int*)  d_in[1];
    const float* enc_emb   = (const float*)d_in[2];
    const float* enc_Wih_f = (const float*)d_in[3];
    const float* enc_Whh_f = (const float*)d_in[4];
    const float* enc_bih_f = (const float*)d_in[5];
    const float* enc_bhh_f = (const float*)d_in[6];
    const float* enc_Wih_b = (const float*)d_in[7];
    const float* enc_Whh_b = (const float*)d_in[8];
    const float* enc_bih_b = (const float*)d_in[9];
    const float* enc_bhh_b = (const float*)d_in[10];
    const float* enc_fcW   = (const float*)d_in[11];
    const float* enc_fcb   = (const float*)d_in[12];
    const float* attn_Wh   = (const float*)d_in[13];
    const float* attn_We   = (const float*)d_in[14];
    const float* attn_b    = (const float*)d_in[15];
    const float* attn_v    = (const float*)d_in[16];
    const float* dec_emb   = (const float*)d_in[17];
    const float* dec_Wih   = (const float*)d_in[18];
    const float* dec_Whh   = (const float*)d_in[19];
    const float* dec_bih   = (const float*)d_in[20];
    const float* dec_bhh   = (const float*)d_in[21];
    const float* fcW       = (const float*)d_in[22];
    const float* fcb       = (const float*)d_in[23];
    float* out = (float*)d_out;

    float* encInF   = symf(g_encInF);
    float* encInB   = symf(g_encInB);
    float* decEmbW  = symf(g_decEmbW);
    float* decEmbFc = symf(g_decEmbFc);
    float* hFa = symf(g_hFa); float* hFb = symf(g_hFb);
    float* hBa = symf(g_hBa); float* hBb = symf(g_hBb);
    float* gh1 = symf(g_gh1); float* gh2 = symf(g_gh2);
    float* encBse  = symf(g_encBse);
    float* encProj = symf(g_encProj);
    float* hcat    = symf(g_hcat);
    float* dhA = symf(g_dhA); float* dhB = symf(g_dhB);
    float* hWhGh = symf(g_hWhGh);
    float* Wcomb = symf(g_Wcomb);
    float* bcomb = symf(g_bcomb);
    float* catAll = symf(g_catAll);

    // zero initial hidden states and output slice 0
    zero_kernel<<<(BB * HH + 255) / 256, 256>>>(hFa, BB * HH);
    zero_kernel<<<(BB * HH + 255) / 256, 256>>>(hBa, BB * HH);
    zero_kernel<<<(BB * VOUT + 255) / 256, 256>>>(out, BB * VOUT);

    // precompute embedding-times-weight tables
    table_kernel<<<(VIN * G3 + 255) / 256, 256>>>(enc_emb, EE, enc_Wih_f, enc_bih_f, encInF, VIN, G3);
    table_kernel<<<(VIN * G3 + 255) / 256, 256>>>(enc_emb, EE, enc_Wih_b, enc_bih_b, encInB, VIN, G3);
    table_kernel<<<(VOUT * G3 + 255) / 256, 256>>>(dec_emb, EE, dec_Wih, dec_bih, decEmbW, VOUT, G3);
    table_kernel<<<(VOUT * VOUT + 255) / 256, 256>>>(dec_emb, EE, fcW + 768 * VOUT, fcb, decEmbFc, VOUT, VOUT);
    build_comb_kernel<<<(HH * 1024 + 255) / 256, 256>>>(attn_Wh, dec_Whh, dec_bhh, Wcomb, bcomb);

    // ---------------- encoder: bidirectional GRU, both directions batched ----------------
    float* hf_in = hFa; float* hf_out = hFb;
    float* hb_in = hBa; float* hb_out = hBb;
    for (int s = 0; s < SS; s++) {
        dim3 grid(G3 / 64, BB / 128, 2);
        sgemm128_kernel<<<grid, 256>>>(hf_in, hb_in, HH,
                                       enc_Whh_f, enc_Whh_b, G3,
                                       gh1, gh2, G3,
                                       HH, enc_bhh_f, enc_bhh_b,
                                       nullptr, nullptr, 0, 0);
        enc_gate_kernel<<<2 * BB, 256>>>(encInF, encInB, src, s,
                                         gh1, gh2, hf_in, hb_in, hf_out, hb_out, encBse);
        { float* t0 = hf_in; hf_in = hf_out; hf_out = t0; }
        { float* t1 = hb_in; hb_in = hb_out; hb_out = t1; }
    }
    // hidden = tanh([hf, hb] @ enc_fcW + enc_fcb)
    concat2_kernel<<<(BB * 512 + 255) / 256, 256>>>(hf_in, HH, hb_in, HH, hcat, BB);
    sgemm(hcat, 512, enc_fcW, HH, dhA, HH, BB, HH, 512, enc_fcb, nullptr, nullptr, 0, 1);

    // enc_proj = enc_bse @ attn_We : (B*S, 512) x (512, 256)
    sgemm(encBse, 512, attn_We, HH, encProj, HH, BB * SS, HH, 512, nullptr, nullptr, nullptr, 0, 0);

    // ---------------- decoder ----------------
    float* h_in = dhA; float* h_out = dhB;
    for (int t = 0; t < TT - 1; t++) {
        float* slot = catAll + (size_t)t * BB * G3;
        // [hWh | gh] = h_in @ [attn_Wh | dec_Whh] + [0 | dec_bhh]
        sgemm(h_in, HH, Wcomb, 1024, hWhGh, 1024, BB, 1024, HH, bcomb, nullptr, nullptr, 0, 0);
        // attention -> weighted written into slot cols [256:768)
        attn_kernel<<<BB, 256>>>(hWhGh, encProj, encBse, attn_b, attn_v, slot);
        // gi = weighted @ dec_Wih[300:812] + decEmbW[trg[t]]  (includes dec_bih)
        sgemm(slot + 256, G3, dec_Wih + EE * G3, G3, gh1, G3, BB, G3, 512,
              nullptr, decEmbW, trg + t * BB, G3, 0);
        // gates: h_out, also written into slot cols [0:256)
        gru_gate_kernel<<<BB * HH / 256, 256>>>(gh1, G3, hWhGh + 256, 1024,
                                                h_in, h_out, slot, G3);
        { float* t2 = h_in; h_in = h_out; h_out = t2; }
    }

    // All logits at once: (24*2048, 768) @ fcW[0:768] + decEmbFc[trg[:-1]]
    sgemm(catAll, G3, fcW, VOUT, out + (size_t)BB * VOUT, VOUT,
          (TT - 1) * BB, VOUT, G3, nullptr, decEmbFc, trg, VOUT, 0);
}

// round 10
// speedup vs baseline: 2.8392x; 1.5494x over previous
#include <cuda_runtime.h>
#include <cuda_bf16.h>
#include <math.h>
#include <stdint.h>

// Problem constants
#define BB 2048
#define SS 24
#define TT 25
#define HH 256
#define EE 300
#define VIN 64
#define VOUT 128
#define G3 768   // 3*H

// ---------------- scratch (device globals; no allocation) ----------------
__device__ float g_encInF[VIN * G3];
__device__ float g_encInB[VIN * G3];
__device__ float g_decEmbW[VOUT * G3];
__device__ float g_decEmbFc[VOUT * VOUT];
__device__ float g_hFa[BB * HH];
__device__ float g_hFb[BB * HH];
__device__ float g_hBa[BB * HH];
__device__ float g_hBb[BB * HH];
__device__ float g_gh1[BB * G3];
__device__ float g_gh2[BB * G3];
__device__ float g_encBse[BB * SS * 2 * HH];   // (B, S, 512)
__device__ float g_encProj[BB * SS * HH];      // (B, S, 256)
__device__ float g_hcat[BB * 2 * HH];
__device__ float g_dhA[BB * HH];
__device__ float g_dhB[BB * HH];
__device__ float g_hWhGh[BB * 1024];           // [hWh(256) | gh(768)] per row
__device__ float g_Wcomb[HH * 1024];           // [attn_Wh | dec_Whh]
__device__ float g_bcomb[1024];                // [0 | dec_bhh]
__device__ float g_catAll[(TT - 1) * BB * G3]; // per-step [h(256) | weighted(512)]

// ---------------- small kernels ----------------
__global__ void zero_kernel(float* p, int n) {
    int i = blockIdx.x * blockDim.x + threadIdx.x;
    if (i < n) p[i] = 0.0f;
}

// All 4 embedding-times-weight tables in one launch.
__global__ void tables_kernel(const float* __restrict__ enc_emb,
                              const float* __restrict__ dec_emb,
                              const float* __restrict__ Wf, const float* __restrict__ bf,
                              const float* __restrict__ Wb, const float* __restrict__ bb2,
                              const float* __restrict__ Wd, const float* __restrict__ bd,
                              const float* __restrict__ Wfc, const float* __restrict__ bfc,
                              float* __restrict__ outF, float* __restrict__ outB,
                              float* __restrict__ outD, float* __restrict__ outFc) {
    int t = blockIdx.x * blockDim.x + threadIdx.x;
    const int nF = VIN * G3, nB = VIN * G3, nD = VOUT * G3, nFc = VOUT * VOUT;
    const float* emb; const float* W; const float* bias; float* out; int v, n, N;
    if (t < nF) {
        emb = enc_emb; W = Wf; bias = bf; out = outF; N = G3; v = t / N; n = t % N;
    } else if (t < nF + nB) {
        t -= nF; emb = enc_emb; W = Wb; bias = bb2; out = outB; N = G3; v = t / N; n = t % N;
    } else if (t < nF + nB + nD) {
        t -= nF + nB; emb = dec_emb; W = Wd; bias = bd; out = outD; N = G3; v = t / N; n = t % N;
    } else if (t < nF + nB + nD + nFc) {
        t -= nF + nB + nD; emb = dec_emb; W = Wfc; bias = bfc; out = outFc; N = VOUT; v = t / N; n = t % N;
    } else return;
    float acc = bias[n];
    const float* er = emb + (size_t)v * EE;
    #pragma unroll 4
    for (int e = 0; e < EE; e++) acc += er[e] * W[(size_t)e * N + n];
    out[(size_t)v * N + n] = acc;
}

__global__ void concat2_kernel(const float* __restrict__ a, int na,
                               const float* __restrict__ b2, int nb,
                               float* __restrict__ dst, int rows) {
    int w = na + nb;
    int t = blockIdx.x * blockDim.x + threadIdx.x;
    if (t >= rows * w) return;
    int r = t / w, c = t % w;
    dst[t] = (c < na) ? a[r * na + c] : b2[r * nb + (c - na)];
}

__global__ void build_comb_kernel(const float* __restrict__ attn_Wh,
                                  const float* __restrict__ dec_Whh,
                                  const float* __restrict__ dec_bhh,
                                  float* __restrict__ W, float* __restrict__ bias) {
    int t = blockIdx.x * blockDim.x + threadIdx.x;
    if (t >= HH * 1024) return;
    int r = t >> 10, c = t & 1023;
    W[t] = (c < HH) ? attn_Wh[r * HH + c] : dec_Whh[r * G3 + (c - HH)];
    if (r == 0) bias[c] = (c < HH) ? 0.0f : dec_bhh[c - HH];
}

// ==================== tensor-core GEMM via mma.sync (baseline PTX) ====================
// CTA tile M=128 x N=64, 256 threads = 8 warps in 4x2 grid of 32x32 warp tiles.
// K chunked by 64. 3-term bf16 split: D += Ahi*Bhi + Ahi*Blo + Alo*Bhi (fp32 acc).
// SMEM: rows of 64 bf16 = 128 bytes, SW128 swizzle.
//   Ahi [0:16384)  Alo [16384:32768)  Bhi(n,k) [32768:40960)  Blo [40960:49152)
#define OFF_AHI  0
#define OFF_ALO  16384
#define OFF_BHI  32768
#define OFF_BLO  40960
#define TC_SMEM  49152

#define SWZ(o) ((o) ^ (((o) >> 3) & 0x70))

__device__ __forceinline__ uint32_t smem_to_u32(const void* smem_ptr) {
    uint32_t addr;
    asm("{ .reg .u64 tmp; cvta.to.shared.u64 tmp, %1; cvt.u32.u64 %0, tmp; }"
        : "=r"(addr) : "l"(smem_ptr));
    return addr;
}

__device__ __forceinline__ void ldsm_x4(uint32_t* r, uint32_t addr) {
    asm volatile("ldmatrix.sync.aligned.m8n8.x4.shared.b16 {%0,%1,%2,%3}, [%4];"
        : "=r"(r[0]), "=r"(r[1]), "=r"(r[2]), "=r"(r[3]) : "r"(addr));
}

__device__ __forceinline__ void mma_bf16(float* c, const uint32_t* a,
                                         uint32_t b0, uint32_t b1) {
    asm volatile(
        "mma.sync.aligned.m16n8k16.row.col.f32.bf16.bf16.f32 "
        "{%0,%1,%2,%3}, {%4,%5,%6,%7}, {%8,%9}, {%0,%1,%2,%3};"
        : "+f"(c[0]), "+f"(c[1]), "+f"(c[2]), "+f"(c[3])
        : "r"(a[0]), "r"(a[1]), "r"(a[2]), "r"(a[3]), "r"(b0), "r"(b1));
}

__device__ __forceinline__ void split2(float x, float y, uint32_t& hi, uint32_t& lo) {
    __nv_bfloat16 hx = __float2bfloat16(x), hy = __float2bfloat16(y);
    float lxf = x - __bfloat162float(hx);
    float lyf = y - __bfloat162float(hy);
    __nv_bfloat16 lx = __float2bfloat16(lxf), ly = __float2bfloat16(lyf);
    hi = (uint32_t)__bfloat16_as_ushort(hx) | ((uint32_t)__bfloat16_as_ushort(hy) << 16);
    lo = (uint32_t)__bfloat16_as_ushort(lx) | ((uint32_t)__bfloat16_as_ushort(ly) << 16);
}

__global__ __launch_bounds__(256) void tc_gemm_kernel(
    const float* __restrict__ A0, const float* __restrict__ A1, int lda,
    const float* __restrict__ B0, const float* __restrict__ B1, int ldb,
    float* __restrict__ C0, float* __restrict__ C1, int ldc,
    int K,
    const float* __restrict__ bias0, const float* __restrict__ bias1,
    const float* __restrict__ gtab, const int* __restrict__ gidx, int gld,
    int act) {
    extern __shared__ char smem[];
    uint32_t sb = smem_to_u32(smem);
    const float* A = blockIdx.z ? A1 : A0;
    const float* Bm = blockIdx.z ? B1 : B0;
    float* C = blockIdx.z ? C1 : C0;
    const float* bias = blockIdx.z ? bias1 : bias0;

    int tid = threadIdx.x;
    int wid = tid >> 5, lane = tid & 31;
    int wr = wid >> 1, wc = wid & 1;           // warp tile: rows [wr*32,+32), cols [wc*32,+32)
    int row0 = blockIdx.y * 128, col0 = blockIdx.x * 64;

    float acc[2][4][4] = {};                   // [rt 16-row tile][ct 8-col tile][frag]

    // ldmatrix lane address components
    int a_r  = wr * 32 + (lane & 15);          // + rt*16
    int a_kp = (lane >> 4) * 16;               // byte offset of k-half within k-step
    int b_n  = wc * 32 + ((lane >> 4) << 3) + (lane & 7);  // + cp*16
    int b_kp = ((lane >> 3) & 1) * 16;

    for (int kc = 0; kc < K; kc += 64) {
        // ---- stage A chunk: 128 rows x 64 k fp32 -> hi/lo bf16, swizzled ----
        #pragma unroll
        for (int it = 0; it < 8; it++) {
            int q = tid + it * 256;            // 0..2047
            int r = q >> 4;                    // 0..127
            int k4 = (q & 15) * 4;             // 0..60
            float4 v = *reinterpret_cast<const float4*>(
                &A[(size_t)(row0 + r) * lda + kc + k4]);
            uint32_t h01, l01, h23, l23;
            split2(v.x, v.y, h01, l01);
            split2(v.z, v.w, h23, l23);
            uint32_t off = SWZ((uint32_t)(r * 128 + k4 * 2));
            *reinterpret_cast<uint2*>(smem + OFF_AHI + off) = make_uint2(h01, h23);
            *reinterpret_cast<uint2*>(smem + OFF_ALO + off) = make_uint2(l01, l23);
        }
        // ---- stage B chunk: 64 n x 64 k (transpose from (K,N) gmem) ----
        {
            int n = tid & 63;
            int kh = tid >> 6;                 // 0..3 -> k block of 16
            #pragma unroll
            for (int i = 0; i < 8; i++) {
                int k = kh * 16 + i * 2;
                float b0f = Bm[(size_t)(kc + k) * ldb + col0 + n];
                float b1f = Bm[(size_t)(kc + k + 1) * ldb + col0 + n];
                uint32_t h, l;
                split2(b0f, b1f, h, l);
                uint32_t off = SWZ((uint32_t)(n * 128 + k * 2));
                *reinterpret_cast<uint32_t*>(smem + OFF_BHI + off) = h;
                *reinterpret_cast<uint32_t*>(smem + OFF_BLO + off) = l;
            }
        }
        __syncthreads();

        // ---- compute: 4 k-steps of K=16 ----
        #pragma unroll
        for (int ks = 0; ks < 4; ks++) {
            uint32_t ah[2][4], al[2][4];
            #pragma unroll
            for (int rt = 0; rt < 2; rt++) {
                int r = a_r + rt * 16;
                uint32_t off = (uint32_t)(r * 128) +
                               (uint32_t)((ks * 32 + a_kp) ^ ((r & 7) << 4));
                ldsm_x4(ah[rt], sb + OFF_AHI + off);
                ldsm_x4(al[rt], sb + OFF_ALO + off);
            }
            uint32_t bh[2][4], bl[2][4];       // cp covers ct {0,1} / {2,3}
            #pragma unroll
            for (int cp = 0; cp < 2; cp++) {
                int n = b_n + cp * 16;
                uint32_t off = (uint32_t)(n * 128) +
                               (uint32_t)((ks * 32 + b_kp) ^ ((n & 7) << 4));
                ldsm_x4(bh[cp], sb + OFF_BHI + off);
                ldsm_x4(bl[cp], sb + OFF_BLO + off);
            }
            #pragma unroll
            for (int rt = 0; rt < 2; rt++)
                #pragma unroll
                for (int ct = 0; ct < 4; ct++) {
                    int cp = ct >> 1, o = (ct & 1) * 2;
                    mma_bf16(acc[rt][ct], ah[rt], bh[cp][o], bh[cp][o + 1]);
                    mma_bf16(acc[rt][ct], ah[rt], bl[cp][o], bl[cp][o + 1]);
                    mma_bf16(acc[rt][ct], al[rt], bh[cp][o], bh[cp][o + 1]);
                }
        }
        __syncthreads();
    }

    // ---- epilogue ----
    #pragma unroll
    for (int rt = 0; rt < 2; rt++) {
        int m0 = row0 + wr * 32 + rt * 16 + (lane >> 2);
        int m1 = m0 + 8;
        const float* g0 = gtab ? (gtab + (size_t)gidx[m0] * gld) : nullptr;
        const float* g1 = gtab ? (gtab + (size_t)gidx[m1] * gld) : nullptr;
        #pragma unroll
        for (int ct = 0; ct < 4; ct++) {
            int n = col0 + wc * 32 + ct * 8 + (lane & 3) * 2;
            float v0 = acc[rt][ct][0], v1 = acc[rt][ct][1];
            float v2 = acc[rt][ct][2], v3 = acc[rt][ct][3];
            if (bias) { float b0 = bias[n], b1 = bias[n + 1]; v0 += b0; v1 += b1; v2 += b0; v3 += b1; }
            if (g0) { v0 += g0[n]; v1 += g0[n + 1]; }
            if (g1) { v2 += g1[n]; v3 += g1[n + 1]; }
            if (act) { v0 = tanhf(v0); v1 = tanhf(v1); v2 = tanhf(v2); v3 = tanhf(v3); }
            *reinterpret_cast<float2*>(&C[(size_t)m0 * ldc + n]) = make_float2(v0, v1);
            *reinterpret_cast<float2*>(&C[(size_t)m1 * ldc + n]) = make_float2(v2, v3);
        }
    }
}

// ---------------- GRU gate kernels ----------------
__global__ void gru_gate_kernel(const float* __restrict__ gi, int gild,
                                const float* __restrict__ gh, int ghld,
                                const float* __restrict__ hprev,
                                float* __restrict__ hout,
                                float* __restrict__ seqdst, int seqStride) {
    int t = blockIdx.x * blockDim.x + threadIdx.x;
    int b = t >> 8;
    int j = t & 255;
    const float* g = gi + (size_t)b * gild;
    const float* G = gh + (size_t)b * ghld;
    float gr = g[j], gz = g[j + HH], gn = g[j + 2 * HH];
    float hr = G[j], hz = G[j + HH], hn2 = G[j + 2 * HH];
    float r = 1.0f / (1.0f + __expf(-(gr + hr)));
    float z = 1.0f / (1.0f + __expf(-(gz + hz)));
    float n = tanhf(gn + r * hn2);
    float hp = hprev[b * HH + j];
    float hv = (1.0f - z) * n + z * hp;
    hout[b * HH + j] = hv;
    if (seqdst) seqdst[(size_t)b * seqStride + j] = hv;
}

__global__ void enc_gate_kernel(const float* __restrict__ giTabF,
                                const float* __restrict__ giTabB,
                                const int* __restrict__ src, int s,
                                const float* __restrict__ ghF,
                                const float* __restrict__ ghB,
                                const float* __restrict__ hprevF,
                                const float* __restrict__ hprevB,
                                float* __restrict__ houtF,
                                float* __restrict__ houtB,
                                float* __restrict__ encBse) {
    int dir = blockIdx.x >> 11;
    int b = blockIdx.x & (BB - 1);
    int j = threadIdx.x;
    int step = dir ? (SS - 1 - s) : s;
    int tok = src[step * BB + b];
    const float* g = (dir ? giTabB : giTabF) + (size_t)tok * G3;
    const float* G = (dir ? ghB : ghF) + (size_t)b * G3;
    float r = 1.0f / (1.0f + __expf(-(g[j] + G[j])));
    float z = 1.0f / (1.0f + __expf(-(g[j + HH] + G[j + HH])));
    float n = tanhf(g[j + 2 * HH] + r * G[j + 2 * HH]);
    const float* hp = (dir ? hprevB : hprevF) + b * HH;
    float hv = (1.0f - z) * n + z * hp[j];
    (dir ? houtB : houtF)[b * HH + j] = hv;
    encBse[((size_t)b * SS + step) * 512 + dir * 256 + j] = hv;
}

// ---------------- fused attention kernel ----------------
__global__ __launch_bounds__(256) void attn_kernel(
    const float* __restrict__ hWhGh,   // B x 1024 (first 256 = hWh)
    const float* __restrict__ proj,    // B x S x 256
    const float* __restrict__ encBse,  // B x S x 512
    const float* __restrict__ attn_b,  // 256
    const float* __restrict__ attn_v,  // 256
    float* __restrict__ catw) {        // (B x 768) slot base for this step
    int b = blockIdx.x;
    int tid = threadIdx.x;
    __shared__ float hb[256];
    __shared__ float vsh[256];
    __shared__ float sc[SS];
    __shared__ float a_sm[SS];
    hb[tid] = hWhGh[b * 1024 + tid] + attn_b[tid];
    vsh[tid] = attn_v[tid];
    __syncthreads();
    int warp = tid >> 5, lane = tid & 31;
    for (int s = warp; s < SS; s += 8) {
        const float* pr = proj + ((size_t)b * SS + s) * 256;
        float sum = 0.0f;
        #pragma unroll
        for (int i = 0; i < 8; i++) {
            int k = lane + i * 32;
            sum += tanhf(hb[k] + pr[k]) * vsh[k];
        }
        #pragma unroll
        for (int o = 16; o > 0; o >>= 1) sum += __shfl_xor_sync(0xFFFFFFFFu, sum, o);
        if (lane == 0) sc[s] = sum;
    }
    __syncthreads();
    if (warp == 0) {
        float v = (lane < SS) ? sc[lane] : -1e30f;
        float mx = v;
        #pragma unroll
        for (int o = 16; o > 0; o >>= 1) mx = fmaxf(mx, __shfl_xor_sync(0xFFFFFFFFu, mx, o));
        float e = (lane < SS) ? __expf(v - mx) : 0.0f;
        float ssum = e;
        #pragma unroll
        for (int o = 16; o > 0; o >>= 1) ssum += __shfl_xor_sync(0xFFFFFFFFu, ssum, o);
        if (lane < SS) a_sm[lane] = e / ssum;
    }
    __syncthreads();
    #pragma unroll
    for (int it = 0; it < 2; it++) {
        int d = tid + it * 256;
        const float* eb = encBse + (size_t)b * SS * 512 + d;
        float acc = 0.0f;
        #pragma unroll
        for (int s = 0; s < SS; s++) acc += a_sm[s] * eb[s * 512];
        catw[(size_t)b * G3 + 256 + d] = acc;
    }
}

// ---------------- host side ----------------
static inline float* symf(const void* s) {
    void* p = nullptr;
    cudaGetSymbolAddress(&p, s);
    return (float*)p;
}

static void tgemm(const float* A0, const float* A1, int lda,
                  const float* B0, const float* B1, int ldb,
                  float* C0, float* C1, int ldc,
                  int M, int N, int K,
                  const float* b0, const float* b1,
                  const float* gtab, const int* gidx, int gld, int act, int z) {
    dim3 grid(N / 64, M / 128, z);
    tc_gemm_kernel<<<grid, 256, TC_SMEM>>>(A0, A1, lda, B0, B1, ldb, C0, C1, ldc,
                                           K, b0, b1, gtab, gidx, gld, act);
}

extern "C" void kernel_launch(void* const* d_in, const int* in_sizes, int n_in,
                              void* d_out, int out_size) {
    const int*   src       = (const int*)  d_in[0];
    const int*   trg       = (const int*)  d_in[1];
    const float* enc_emb   = (const float*)d_in[2];
    const float* enc_Wih_f = (const float*)d_in[3];
    const float* enc_Whh_f = (const float*)d_in[4];
    const float* enc_bih_f = (const float*)d_in[5];
    const float* enc_bhh_f = (const float*)d_in[6];
    const float* enc_Wih_b = (const float*)d_in[7];
    const float* enc_Whh_b = (const float*)d_in[8];
    const float* enc_bih_b = (const float*)d_in[9];
    const float* enc_bhh_b = (const float*)d_in[10];
    const float* enc_fcW   = (const float*)d_in[11];
    const float* enc_fcb   = (const float*)d_in[12];
    const float* attn_Wh   = (const float*)d_in[13];
    const float* attn_We   = (const float*)d_in[14];
    const float* attn_b    = (const float*)d_in[15];
    const float* attn_v    = (const float*)d_in[16];
    const float* dec_emb   = (const float*)d_in[17];
    const float* dec_Wih   = (const float*)d_in[18];
    const float* dec_Whh   = (const float*)d_in[19];
    const float* dec_bih   = (const float*)d_in[20];
    const float* dec_bhh   = (const float*)d_in[21];
    const float* fcW       = (const float*)d_in[22];
    const float* fcb       = (const float*)d_in[23];
    float* out = (float*)d_out;

    cudaFuncSetAttribute(tc_gemm_kernel,
                         cudaFuncAttributeMaxDynamicSharedMemorySize, TC_SMEM);

    float* encInF   = symf(g_encInF);
    float* encInB   = symf(g_encInB);
    float* decEmbW  = symf(g_decEmbW);
    float* decEmbFc = symf(g_decEmbFc);
    float* hFa = symf(g_hFa); float* hFb = symf(g_hFb);
    float* hBa = symf(g_hBa); float* hBb = symf(g_hBb);
    float* gh1 = symf(g_gh1); float* gh2 = symf(g_gh2);
    float* encBse  = symf(g_encBse);
    float* encProj = symf(g_encProj);
    float* hcat    = symf(g_hcat);
    float* dhA = symf(g_dhA); float* dhB = symf(g_dhB);
    float* hWhGh = symf(g_hWhGh);
    float* Wcomb = symf(g_Wcomb);
    float* bcomb = symf(g_bcomb);
    float* catAll = symf(g_catAll);

    // zero initial hidden states and output slice 0
    zero_kernel<<<(BB * HH + 255) / 256, 256>>>(hFa, BB * HH);
    zero_kernel<<<(BB * HH + 255) / 256, 256>>>(hBa, BB * HH);
    zero_kernel<<<(BB * VOUT + 255) / 256, 256>>>(out, BB * VOUT);

    // all 4 embedding-times-weight tables in one launch
    {
        int total = VIN * G3 * 2 + VOUT * G3 + VOUT * VOUT;
        tables_kernel<<<(total + 255) / 256, 256>>>(
            enc_emb, dec_emb,
            enc_Wih_f, enc_bih_f, enc_Wih_b, enc_bih_b,
            dec_Wih, dec_bih, fcW + 768 * VOUT, fcb,
            encInF, encInB, decEmbW, decEmbFc);
    }
    build_comb_kernel<<<(HH * 1024 + 255) / 256, 256>>>(attn_Wh, dec_Whh, dec_bhh, Wcomb, bcomb);

    // ---------------- encoder: bidirectional GRU, both directions batched ----------------
    float* hf_in = hFa; float* hf_out = hFb;
    float* hb_in = hBa; float* hb_out = hBb;
    for (int s = 0; s < SS; s++) {
        tgemm(hf_in, hb_in, HH, enc_Whh_f, enc_Whh_b, G3, gh1, gh2, G3,
              BB, G3, HH, enc_bhh_f, enc_bhh_b, nullptr, nullptr, 0, 0, 2);
        enc_gate_kernel<<<2 * BB, 256>>>(encInF, encInB, src, s,
                                         gh1, gh2, hf_in, hb_in, hf_out, hb_out, encBse);
        { float* t0 = hf_in; hf_in = hf_out; hf_out = t0; }
        { float* t1 = hb_in; hb_in = hb_out; hb_out = t1; }
    }
    // hidden = tanh([hf, hb] @ enc_fcW + enc_fcb)
    concat2_kernel<<<(BB * 512 + 255) / 256, 256>>>(hf_in, HH, hb_in, HH, hcat, BB);
    tgemm(hcat, nullptr, 512, enc_fcW, nullptr, HH, dhA, nullptr, HH,
          BB, HH, 512, enc_fcb, nullptr, nullptr, nullptr, 0, 1, 1);

    // enc_proj = enc_bse @ attn_We : (B*S, 512) x (512, 256)
    tgemm(encBse, nullptr, 512, attn_We, nullptr, HH, encProj, nullptr, HH,
          BB * SS, HH, 512, nullptr, nullptr, nullptr, nullptr, 0, 0, 1);

    // ---------------- decoder ----------------
    float* h_in = dhA; float* h_out = dhB;
    for (int t = 0; t < TT - 1; t++) {
        float* slot = catAll + (size_t)t * BB * G3;
        // [hWh | gh] = h_in @ [attn_Wh | dec_Whh] + [0 | dec_bhh]
        tgemm(h_in, nullptr, HH, Wcomb, nullptr, 1024, hWhGh, nullptr, 1024,
              BB, 1024, HH, bcomb, nullptr, nullptr, nullptr, 0, 0, 1);
        // attention -> weighted written into slot cols [256:768)
        attn_kernel<<<BB, 256>>>(hWhGh, encProj, encBse, attn_b, attn_v, slot);
        // gi = weighted @ dec_Wih[300:812] + decEmbW[trg[t]]  (includes dec_bih)
        tgemm(slot + 256, nullptr, G3, dec_Wih + EE * G3, nullptr, G3, gh1, nullptr, G3,
              BB, G3, 512, nullptr, nullptr, decEmbW, trg + t * BB, G3, 0, 1);
        // gates -> h_out, slot cols [0:256)
        gru_gate_kernel<<<BB * HH / 256, 256>>>(gh1, G3, hWhGh + 256, 1024,
                                                h_in, h_out, slot, G3);
        { float* t2 = h_in; h_in = h_out; h_out = t2; }
    }

    // All logits at once: (24*2048, 768) @ fcW[0:768] + decEmbFc[trg[:-1]]
    tgemm(catAll, nullptr, G3, fcW, nullptr, VOUT, out + (size_t)BB * VOUT, nullptr, VOUT,
          (TT - 1) * BB, VOUT, G3, nullptr, nullptr, decEmbFc, trg, VOUT, 0, 1);
}

// round 11
// speedup vs baseline: 3.2264x; 1.1364x over previous
#include <cuda_runtime.h>
#include <cuda_bf16.h>
#include <math.h>
#include <stdint.h>

// Problem constants
#define BB 2048
#define SS 24
#define TT 25
#define HH 256
#define EE 300
#define VIN 64
#define VOUT 128
#define G3 768   // 3*H

typedef __nv_bfloat16 bf16;

// ---------------- scratch (device globals; no allocation) ----------------
__device__ float g_encInF[VIN * G3];
__device__ float g_encInB[VIN * G3];
__device__ float g_decEmbW[VOUT * G3];
__device__ float g_decEmbFc[VOUT * VOUT];
__device__ float g_hFa[BB * HH];
__device__ float g_hFb[BB * HH];
__device__ float g_hBa[BB * HH];
__device__ float g_hBb[BB * HH];
__device__ float g_gh1[BB * G3];
__device__ float g_gh2[BB * G3];
__device__ float g_encBse[BB * SS * 2 * HH];   // (B, S, 512) fp32
__device__ float g_encProj[BB * SS * HH];      // (B, S, 256) fp32
__device__ float g_hcat[BB * 2 * HH];
__device__ float g_dhA[BB * HH];
__device__ float g_dhB[BB * HH];
__device__ float g_hWhGh[BB * 1024];           // [hWh(256) | gh(768)] per row
__device__ float g_bcomb[1024];                // [0 | dec_bhh]

// bf16 pair planes (hi / lo), all k-contiguous
__device__ bf16 g_hFaHi[BB * HH]; __device__ bf16 g_hFaLo[BB * HH];
__device__ bf16 g_hFbHi[BB * HH]; __device__ bf16 g_hFbLo[BB * HH];
__device__ bf16 g_hBaHi[BB * HH]; __device__ bf16 g_hBaLo[BB * HH];
__device__ bf16 g_hBbHi[BB * HH]; __device__ bf16 g_hBbLo[BB * HH];
__device__ bf16 g_dhAHi[BB * HH]; __device__ bf16 g_dhALo[BB * HH];
__device__ bf16 g_dhBHi[BB * HH]; __device__ bf16 g_dhBLo[BB * HH];
__device__ bf16 g_WfHi[G3 * HH];  __device__ bf16 g_WfLo[G3 * HH];     // (768,256)
__device__ bf16 g_WbHi[G3 * HH];  __device__ bf16 g_WbLo[G3 * HH];     // (768,256)
__device__ bf16 g_WcombHi[1024 * HH]; __device__ bf16 g_WcombLo[1024 * HH]; // (1024,256)
__device__ bf16 g_Wih2Hi[G3 * 512];   __device__ bf16 g_Wih2Lo[G3 * 512];   // (768,512)
__device__ bf16 g_fcW1Hi[VOUT * G3];  __device__ bf16 g_fcW1Lo[VOUT * G3];  // (128,768)
__device__ bf16 g_catHi[(TT - 1) * BB * G3];
__device__ bf16 g_catLo[(TT - 1) * BB * G3];

__device__ __forceinline__ void split1(float x, bf16& h, bf16& l) {
    h = __float2bfloat16(x);
    l = __float2bfloat16(x - __bfloat162float(h));
}

// ---------------- small kernels ----------------
__global__ void zero_kernel(float* p, int n) {
    int i = blockIdx.x * blockDim.x + threadIdx.x;
    if (i < n) p[i] = 0.0f;
}

__global__ void split_kernel(const float* __restrict__ src,
                             bf16* __restrict__ hi, bf16* __restrict__ lo, int n) {
    int i = blockIdx.x * blockDim.x + threadIdx.x;
    if (i >= n) return;
    bf16 h, l; split1(src[i], h, l);
    hi[i] = h; lo[i] = l;
}

// transpose+split weight: W (K,N) fp32 -> out (N,K) bf16 hi/lo
__global__ void wsplit_kernel(const float* __restrict__ W, int K, int N,
                              bf16* __restrict__ hi, bf16* __restrict__ lo) {
    int t = blockIdx.x * blockDim.x + threadIdx.x;
    if (t >= K * N) return;
    int k = t / N, n = t % N;
    bf16 h, l; split1(W[t], h, l);
    hi[(size_t)n * K + k] = h;
    lo[(size_t)n * K + k] = l;
}

// Wcomb pairs (1024,256) + bcomb
__global__ void comb_split_kernel(const float* __restrict__ attn_Wh,
                                  const float* __restrict__ dec_Whh,
                                  const float* __restrict__ dec_bhh,
                                  bf16* __restrict__ hi, bf16* __restrict__ lo,
                                  float* __restrict__ bias) {
    int t = blockIdx.x * blockDim.x + threadIdx.x;
    if (t >= HH * 1024) return;
    int k = t >> 10, c = t & 1023;
    float v = (c < HH) ? attn_Wh[k * HH + c] : dec_Whh[k * G3 + (c - HH)];
    bf16 h, l; split1(v, h, l);
    hi[(size_t)c * HH + k] = h;
    lo[(size_t)c * HH + k] = l;
    if (k == 0) bias[c] = (c < HH) ? 0.0f : dec_bhh[c - HH];
}

// All 4 embedding-times-weight tables in one launch.
__global__ void tables_kernel(const float* __restrict__ enc_emb,
                              const float* __restrict__ dec_emb,
                              const float* __restrict__ Wf, const float* __restrict__ bf,
                              const float* __restrict__ Wb, const float* __restrict__ bb2,
                              const float* __restrict__ Wd, const float* __restrict__ bd,
                              const float* __restrict__ Wfc, const float* __restrict__ bfc,
                              float* __restrict__ outF, float* __restrict__ outB,
                              float* __restrict__ outD, float* __restrict__ outFc) {
    int t = blockIdx.x * blockDim.x + threadIdx.x;
    const int nF = VIN * G3, nB = VIN * G3, nD = VOUT * G3, nFc = VOUT * VOUT;
    const float* emb; const float* W; const float* bias; float* out; int v, n, N;
    if (t < nF) {
        emb = enc_emb; W = Wf; bias = bf; out = outF; N = G3; v = t / N; n = t % N;
    } else if (t < nF + nB) {
        t -= nF; emb = enc_emb; W = Wb; bias = bb2; out = outB; N = G3; v = t / N; n = t % N;
    } else if (t < nF + nB + nD) {
        t -= nF + nB; emb = dec_emb; W = Wd; bias = bd; out = outD; N = G3; v = t / N; n = t % N;
    } else if (t < nF + nB + nD + nFc) {
        t -= nF + nB + nD; emb = dec_emb; W = Wfc; bias = bfc; out = outFc; N = VOUT; v = t / N; n = t % N;
    } else return;
    float acc = bias[n];
    const float* er = emb + (size_t)v * EE;
    #pragma unroll 4
    for (int e = 0; e < EE; e++) acc += er[e] * W[(size_t)e * N + n];
    out[(size_t)v * N + n] = acc;
}

__global__ void concat2_kernel(const float* __restrict__ a, int na,
                               const float* __restrict__ b2, int nb,
                               float* __restrict__ dst, int rows) {
    int w = na + nb;
    int t = blockIdx.x * blockDim.x + threadIdx.x;
    if (t >= rows * w) return;
    int r = t / w, c = t % w;
    dst[t] = (c < na) ? a[r * na + c] : b2[r * nb + (c - na)];
}

// ==================== shared mma helpers ====================
#define SWZ(o) ((o) ^ (((o) >> 3) & 0x70))

__device__ __forceinline__ uint32_t smem_to_u32(const void* smem_ptr) {
    uint32_t addr;
    asm("{ .reg .u64 tmp; cvta.to.shared.u64 tmp, %1; cvt.u32.u64 %0, tmp; }"
        : "=r"(addr) : "l"(smem_ptr));
    return addr;
}

__device__ __forceinline__ void ldsm_x4(uint32_t* r, uint32_t addr) {
    asm volatile("ldmatrix.sync.aligned.m8n8.x4.shared.b16 {%0,%1,%2,%3}, [%4];"
        : "=r"(r[0]), "=r"(r[1]), "=r"(r[2]), "=r"(r[3]) : "r"(addr));
}

__device__ __forceinline__ void mma_bf16(float* c, const uint32_t* a,
                                         uint32_t b0, uint32_t b1) {
    asm volatile(
        "mma.sync.aligned.m16n8k16.row.col.f32.bf16.bf16.f32 "
        "{%0,%1,%2,%3}, {%4,%5,%6,%7}, {%8,%9}, {%0,%1,%2,%3};"
        : "+f"(c[0]), "+f"(c[1]), "+f"(c[2]), "+f"(c[3])
        : "r"(a[0]), "r"(a[1]), "r"(a[2]), "r"(a[3]), "r"(b0), "r"(b1));
}

__device__ __forceinline__ void split2(float x, float y, uint32_t& hi, uint32_t& lo) {
    bf16 hx = __float2bfloat16(x), hy = __float2bfloat16(y);
    float lxf = x - __bfloat162float(hx);
    float lyf = y - __bfloat162float(hy);
    bf16 lx = __float2bfloat16(lxf), ly = __float2bfloat16(lyf);
    hi = (uint32_t)__bfloat16_as_ushort(hx) | ((uint32_t)__bfloat16_as_ushort(hy) << 16);
    lo = (uint32_t)__bfloat16_as_ushort(lx) | ((uint32_t)__bfloat16_as_ushort(ly) << 16);
}

__device__ __forceinline__ void cpasync16(uint32_t s, const void* g) {
    asm volatile("cp.async.cg.shared.global [%0], [%1], 16;" :: "r"(s), "l"(g));
}
#define CP_COMMIT() asm volatile("cp.async.commit_group;" ::: "memory")
#define CP_WAIT0()  asm volatile("cp.async.wait_group 0;" ::: "memory")

// ==================== pair-operand tensor-core GEMM ====================
// A: M x K bf16 hi/lo planes (row-major k-contig). B: N x K bf16 hi/lo planes.
// CTA tile 128x64, 8 warps (4x2 of 32x32). K chunked by 64, 2-stage cp.async pipeline.
// 3-term: D += AhiBhi + AhiBlo + AloBhi, fp32 acc.
#define OFF_AHI  0
#define OFF_ALO  16384
#define OFF_BHI  32768
#define OFF_BLO  40960
#define PSTG     49152
#define PAIR_SMEM (2 * PSTG)

#define STAGE_CHUNK(kcv, stv) do {                                             \
    uint32_t _sbase = sb + (uint32_t)(stv) * PSTG;                             \
    _Pragma("unroll")                                                          \
    for (int _it = 0; _it < 4; _it++) {                                        \
        int _q = tid + _it * 256; int _r = _q >> 3, _j = _q & 7;               \
        size_t _go = (size_t)(row0 + _r) * lda + (kcv) + _j * 8;               \
        uint32_t _so = SWZ((uint32_t)(_r * 128 + _j * 16));                    \
        cpasync16(_sbase + OFF_AHI + _so, AH + _go);                           \
        cpasync16(_sbase + OFF_ALO + _so, AL + _go);                           \
    }                                                                          \
    _Pragma("unroll")                                                          \
    for (int _it = 0; _it < 2; _it++) {                                        \
        int _q = tid + _it * 256; int _r = _q >> 3, _j = _q & 7;               \
        size_t _go = (size_t)(col0 + _r) * ldb + (kcv) + _j * 8;               \
        uint32_t _so = SWZ((uint32_t)(_r * 128 + _j * 16));                    \
        cpasync16(_sbase + OFF_BHI + _so, BH + _go);                           \
        cpasync16(_sbase + OFF_BLO + _so, BL + _go);                           \
    }                                                                          \
    CP_COMMIT();                                                               \
} while (0)

__global__ __launch_bounds__(256) void tc_gemm_pair(
    const bf16* __restrict__ AH0, const bf16* __restrict__ AL0,
    const bf16* __restrict__ AH1, const bf16* __restrict__ AL1, int lda,
    const bf16* __restrict__ BH0, const bf16* __restrict__ BL0,
    const bf16* __restrict__ BH1, const bf16* __restrict__ BL1, int ldb,
    float* __restrict__ C0, float* __restrict__ C1, int ldc, int K,
    const float* __restrict__ bias0, const float* __restrict__ bias1,
    const float* __restrict__ gtab, const int* __restrict__ gidx, int gld) {
    extern __shared__ char smem[];
    uint32_t sb = smem_to_u32(smem);
    const bf16* AH = blockIdx.z ? AH1 : AH0;
    const bf16* AL = blockIdx.z ? AL1 : AL0;
    const bf16* BH = blockIdx.z ? BH1 : BH0;
    const bf16* BL = blockIdx.z ? BL1 : BL0;
    float* C = blockIdx.z ? C1 : C0;
    const float* bias = blockIdx.z ? bias1 : bias0;

    int tid = threadIdx.x;
    int wid = tid >> 5, lane = tid & 31;
    int wr = wid >> 1, wc = wid & 1;
    int row0 = blockIdx.y * 128, col0 = blockIdx.x * 64;

    float acc[2][4][4] = {};

    int a_r  = wr * 32 + (lane & 15);
    int a_kp = (lane >> 4) * 16;
    int b_n  = wc * 32 + ((lane >> 4) << 3) + (lane & 7);
    int b_kp = ((lane >> 3) & 1) * 16;

    int nc = K >> 6;
    STAGE_CHUNK(0, 0);
    CP_WAIT0();
    __syncthreads();

    for (int c = 0; c < nc; c++) {
        int cur = c & 1;
        if (c + 1 < nc) STAGE_CHUNK((c + 1) << 6, cur ^ 1);

        uint32_t sb2 = sb + (uint32_t)cur * PSTG;
        #pragma unroll
        for (int ks = 0; ks < 4; ks++) {
            uint32_t ah[2][4], al[2][4];
            #pragma unroll
            for (int rt = 0; rt < 2; rt++) {
                int r = a_r + rt * 16;
                uint32_t off = (uint32_t)(r * 128) +
                               (uint32_t)((ks * 32 + a_kp) ^ ((r & 7) << 4));
                ldsm_x4(ah[rt], sb2 + OFF_AHI + off);
                ldsm_x4(al[rt], sb2 + OFF_ALO + off);
            }
            uint32_t bh[2][4], bl[2][4];
            #pragma unroll
            for (int cp = 0; cp < 2; cp++) {
                int n = b_n + cp * 16;
                uint32_t off = (uint32_t)(n * 128) +
                               (uint32_t)((ks * 32 + b_kp) ^ ((n & 7) << 4));
                ldsm_x4(bh[cp], sb2 + OFF_BHI + off);
                ldsm_x4(bl[cp], sb2 + OFF_BLO + off);
            }
            #pragma unroll
            for (int rt = 0; rt < 2; rt++)
                #pragma unroll
                for (int ct = 0; ct < 4; ct++) {
                    int cp = ct >> 1, o = (ct & 1) * 2;
                    mma_bf16(acc[rt][ct], ah[rt], bh[cp][o], bh[cp][o + 1]);
                    mma_bf16(acc[rt][ct], ah[rt], bl[cp][o], bl[cp][o + 1]);
                    mma_bf16(acc[rt][ct], al[rt], bh[cp][o], bh[cp][o + 1]);
                }
        }
        if (c + 1 < nc) CP_WAIT0();
        __syncthreads();
    }

    // epilogue
    #pragma unroll
    for (int rt = 0; rt < 2; rt++) {
        int m0 = row0 + wr * 32 + rt * 16 + (lane >> 2);
        int m1 = m0 + 8;
        const float* g0 = gtab ? (gtab + (size_t)gidx[m0] * gld) : nullptr;
        const float* g1 = gtab ? (gtab + (size_t)gidx[m1] * gld) : nullptr;
        #pragma unroll
        for (int ct = 0; ct < 4; ct++) {
            int n = col0 + wc * 32 + ct * 8 + (lane & 3) * 2;
            float v0 = acc[rt][ct][0], v1 = acc[rt][ct][1];
            float v2 = acc[rt][ct][2], v3 = acc[rt][ct][3];
            if (bias) { float b0 = bias[n], b1 = bias[n + 1]; v0 += b0; v1 += b1; v2 += b0; v3 += b1; }
            if (g0) { v0 += g0[n]; v1 += g0[n + 1]; }
            if (g1) { v2 += g1[n]; v3 += g1[n + 1]; }
            *reinterpret_cast<float2*>(&C[(size_t)m0 * ldc + n]) = make_float2(v0, v1);
            *reinterpret_cast<float2*>(&C[(size_t)m1 * ldc + n]) = make_float2(v2, v3);
        }
    }
}

// ==================== fp32-operand tensor-core GEMM (R10 proven) ====================
// Used for one-off GEMMs (enc_fc, encProj) whose operands are fp32-only.
#define F32_SMEM 49152

__global__ __launch_bounds__(256) void tc_gemm_f32(
    const float* __restrict__ A, int lda,
    const float* __restrict__ Bm, int ldb,
    float* __restrict__ C, int ldc,
    int K, const float* __restrict__ bias, int act) {
    extern __shared__ char smem[];
    uint32_t sb = smem_to_u32(smem);

    int tid = threadIdx.x;
    int wid = tid >> 5, lane = tid & 31;
    int wr = wid >> 1, wc = wid & 1;
    int row0 = blockIdx.y * 128, col0 = blockIdx.x * 64;

    float acc[2][4][4] = {};

    int a_r  = wr * 32 + (lane & 15);
    int a_kp = (lane >> 4) * 16;
    int b_n  = wc * 32 + ((lane >> 4) << 3) + (lane & 7);
    int b_kp = ((lane >> 3) & 1) * 16;

    for (int kc = 0; kc < K; kc += 64) {
        #pragma unroll
        for (int it = 0; it < 8; it++) {
            int q = tid + it * 256;
            int r = q >> 4;
            int k4 = (q & 15) * 4;
            float4 v = *reinterpret_cast<const float4*>(
                &A[(size_t)(row0 + r) * lda + kc + k4]);
            uint32_t h01, l01, h23, l23;
            split2(v.x, v.y, h01, l01);
            split2(v.z, v.w, h23, l23);
            uint32_t off = SWZ((uint32_t)(r * 128 + k4 * 2));
            *reinterpret_cast<uint2*>(smem + OFF_AHI + off) = make_uint2(h01, h23);
            *reinterpret_cast<uint2*>(smem + OFF_ALO + off) = make_uint2(l01, l23);
        }
        {
            int n = tid & 63;
            int kh = tid >> 6;
            #pragma unroll
            for (int i = 0; i < 8; i++) {
                int k = kh * 16 + i * 2;
                float b0f = Bm[(size_t)(kc + k) * ldb + col0 + n];
                float b1f = Bm[(size_t)(kc + k + 1) * ldb + col0 + n];
                uint32_t h, l;
                split2(b0f, b1f, h, l);
                uint32_t off = SWZ((uint32_t)(n * 128 + k * 2));
                *reinterpret_cast<uint32_t*>(smem + OFF_BHI + off) = h;
                *reinterpret_cast<uint32_t*>(smem + OFF_BLO + off) = l;
            }
        }
        __syncthreads();

        #pragma unroll
        for (int ks = 0; ks < 4; ks++) {
            uint32_t ah[2][4], al[2][4];
            #pragma unroll
            for (int rt = 0; rt < 2; rt++) {
                int r = a_r + rt * 16;
                uint32_t off = (uint32_t)(r * 128) +
                               (uint32_t)((ks * 32 + a_kp) ^ ((r & 7) << 4));
                ldsm_x4(ah[rt], sb + OFF_AHI + off);
                ldsm_x4(al[rt], sb + OFF_ALO + off);
            }
            uint32_t bh[2][4], bl[2][4];
            #pragma unroll
            for (int cp = 0; cp < 2; cp++) {
                int n = b_n + cp * 16;
                uint32_t off = (uint32_t)(n * 128) +
                               (uint32_t)((ks * 32 + b_kp) ^ ((n & 7) << 4));
                ldsm_x4(bh[cp], sb + OFF_BHI + off);
                ldsm_x4(bl[cp], sb + OFF_BLO + off);
            }
            #pragma unroll
            for (int rt = 0; rt < 2; rt++)
                #pragma unroll
                for (int ct = 0; ct < 4; ct++) {
                    int cp = ct >> 1, o = (ct & 1) * 2;
                    mma_bf16(acc[rt][ct], ah[rt], bh[cp][o], bh[cp][o + 1]);
                    mma_bf16(acc[rt][ct], ah[rt], bl[cp][o], bl[cp][o + 1]);
                    mma_bf16(acc[rt][ct], al[rt], bh[cp][o], bh[cp][o + 1]);
                }
        }
        __syncthreads();
    }

    #pragma unroll
    for (int rt = 0; rt < 2; rt++) {
        int m0 = row0 + wr * 32 + rt * 16 + (lane >> 2);
        int m1 = m0 + 8;
        #pragma unroll
        for (int ct = 0; ct < 4; ct++) {
            int n = col0 + wc * 32 + ct * 8 + (lane & 3) * 2;
            float v0 = acc[rt][ct][0], v1 = acc[rt][ct][1];
            float v2 = acc[rt][ct][2], v3 = acc[rt][ct][3];
            if (bias) { float b0 = bias[n], b1 = bias[n + 1]; v0 += b0; v1 += b1; v2 += b0; v3 += b1; }
            if (act) { v0 = tanhf(v0); v1 = tanhf(v1); v2 = tanhf(v2); v3 = tanhf(v3); }
            *reinterpret_cast<float2*>(&C[(size_t)m0 * ldc + n]) = make_float2(v0, v1);
            *reinterpret_cast<float2*>(&C[(size_t)m1 * ldc + n]) = make_float2(v2, v3);
        }
    }
}

// ---------------- GRU gate kernels ----------------
__global__ void gru_gate_kernel(const float* __restrict__ gi, int gild,
                                const float* __restrict__ gh, int ghld,
                                const float* __restrict__ hprev,
                                float* __restrict__ hout,
                                bf16* __restrict__ houtHi, bf16* __restrict__ houtLo,
                                bf16* __restrict__ catHi, bf16* __restrict__ catLo) {
    int t = blockIdx.x * blockDim.x + threadIdx.x;
    int b = t >> 8;
    int j = t & 255;
    const float* g = gi + (size_t)b * gild;
    const float* G = gh + (size_t)b * ghld;
    float r = 1.0f / (1.0f + __expf(-(g[j] + G[j])));
    float z = 1.0f / (1.0f + __expf(-(g[j + HH] + G[j + HH])));
    float n = tanhf(g[j + 2 * HH] + r * G[j + 2 * HH]);
    float hp = hprev[b * HH + j];
    float hv = (1.0f - z) * n + z * hp;
    hout[b * HH + j] = hv;
    bf16 hh, hl; split1(hv, hh, hl);
    houtHi[b * HH + j] = hh;
    houtLo[b * HH + j] = hl;
    catHi[(size_t)b * G3 + j] = hh;
    catLo[(size_t)b * G3 + j] = hl;
}

__global__ void enc_gate_kernel(const float* __restrict__ giTabF,
                                const float* __restrict__ giTabB,
                                const int* __restrict__ src, int s,
                                const float* __restrict__ ghF,
                                const float* __restrict__ ghB,
                                const float* __restrict__ hprevF,
                                const float* __restrict__ hprevB,
                                float* __restrict__ houtF,
                                float* __restrict__ houtB,
                                bf16* __restrict__ houtFHi, bf16* __restrict__ houtFLo,
                                bf16* __restrict__ houtBHi, bf16* __restrict__ houtBLo,
                                float* __restrict__ encBse) {
    int dir = blockIdx.x >> 11;
    int b = blockIdx.x & (BB - 1);
    int j = threadIdx.x;
    int step = dir ? (SS - 1 - s) : s;
    int tok = src[step * BB + b];
    const float* g = (dir ? giTabB : giTabF) + (size_t)tok * G3;
    const float* G = (dir ? ghB : ghF) + (size_t)b * G3;
    float r = 1.0f / (1.0f + __expf(-(g[j] + G[j])));
    float z = 1.0f / (1.0f + __expf(-(g[j + HH] + G[j + HH])));
    float n = tanhf(g[j + 2 * HH] + r * G[j + 2 * HH]);
    const float* hp = (dir ? hprevB : hprevF) + b * HH;
    float hv = (1.0f - z) * n + z * hp[j];
    (dir ? houtB : houtF)[b * HH + j] = hv;
    bf16 hh, hl; split1(hv, hh, hl);
    (dir ? houtBHi : houtFHi)[b * HH + j] = hh;
    (dir ? houtBLo : houtFLo)[b * HH + j] = hl;
    encBse[((size_t)b * SS + step) * 512 + dir * 256 + j] = hv;
}

// ---------------- fused attention kernel ----------------
__global__ __launch_bounds__(256) void attn_kernel(
    const float* __restrict__ hWhGh,   // B x 1024 (first 256 = hWh)
    const float* __restrict__ proj,    // B x S x 256
    const float* __restrict__ encBse,  // B x S x 512
    const float* __restrict__ attn_b,  // 256
    const float* __restrict__ attn_v,  // 256
    bf16* __restrict__ catHi, bf16* __restrict__ catLo) {  // slot base
    int b = blockIdx.x;
    int tid = threadIdx.x;
    __shared__ float hb[256];
    __shared__ float vsh[256];
    __shared__ float sc[SS];
    __shared__ float a_sm[SS];
    hb[tid] = hWhGh[b * 1024 + tid] + attn_b[tid];
    vsh[tid] = attn_v[tid];
    __syncthreads();
    int warp = tid >> 5, lane = tid & 31;
    for (int s = warp; s < SS; s += 8) {
        const float* pr = proj + ((size_t)b * SS + s) * 256;
        float sum = 0.0f;
        #pragma unroll
        for (int i = 0; i < 8; i++) {
            int k = lane + i * 32;
            sum += tanhf(hb[k] + pr[k]) * vsh[k];
        }
        #pragma unroll
        for (int o = 16; o > 0; o >>= 1) sum += __shfl_xor_sync(0xFFFFFFFFu, sum, o);
        if (lane == 0) sc[s] = sum;
    }
    __syncthreads();
    if (warp == 0) {
        float v = (lane < SS) ? sc[lane] : -1e30f;
        float mx = v;
        #pragma unroll
        for (int o = 16; o > 0; o >>= 1) mx = fmaxf(mx, __shfl_xor_sync(0xFFFFFFFFu, mx, o));
        float e = (lane < SS) ? __expf(v - mx) : 0.0f;
        float ssum = e;
        #pragma unroll
        for (int o = 16; o > 0; o >>= 1) ssum += __shfl_xor_sync(0xFFFFFFFFu, ssum, o);
        if (lane < SS) a_sm[lane] = e / ssum;
    }
    __syncthreads();
    #pragma unroll
    for (int it = 0; it < 2; it++) {
        int d = tid + it * 256;
        const float* eb = encBse + (size_t)b * SS * 512 + d;
        float acc = 0.0f;
        #pragma unroll
        for (int s = 0; s < SS; s++) acc += a_sm[s] * eb[s * 512];
        bf16 hh, hl; split1(acc, hh, hl);
        catHi[(size_t)b * G3 + 256 + d] = hh;
        catLo[(size_t)b * G3 + 256 + d] = hl;
    }
}

// ---------------- host side ----------------
static inline float* symf(const void* s) {
    void* p = nullptr;
    cudaGetSymbolAddress(&p, s);
    return (float*)p;
}
static inline bf16* symb(const void* s) {
    void* p = nullptr;
    cudaGetSymbolAddress(&p, s);
    return (bf16*)p;
}

static void pgemm(const bf16* AH0, const bf16* AL0, const bf16* AH1, const bf16* AL1, int lda,
                  const bf16* BH0, const bf16* BL0, const bf16* BH1, const bf16* BL1, int ldb,
                  float* C0, float* C1, int ldc, int M, int N, int K,
                  const float* b0, const float* b1,
                  const float* gtab, const int* gidx, int gld, int z) {
    dim3 grid(N / 64, M / 128, z);
    tc_gemm_pair<<<grid, 256, PAIR_SMEM>>>(AH0, AL0, AH1, AL1, lda,
                                           BH0, BL0, BH1, BL1, ldb,
                                           C0, C1, ldc, K, b0, b1, gtab, gidx, gld);
}

extern "C" void kernel_launch(void* const* d_in, const int* in_sizes, int n_in,
                              void* d_out, int out_size) {
    const int*   src       = (const int*)  d_in[0];
    const int*   trg       = (const int*)  d_in[1];
    const float* enc_emb   = (const float*)d_in[2];
    const float* enc_Wih_f = (const float*)d_in[3];
    const float* enc_Whh_f = (const float*)d_in[4];
    const float* enc_bih_f = (const float*)d_in[5];
    const float* enc_bhh_f = (const float*)d_in[6];
    const float* enc_Wih_b = (const float*)d_in[7];
    const float* enc_Whh_b = (const float*)d_in[8];
    const float* enc_bih_b = (const float*)d_in[9];
    const float* enc_bhh_b = (const float*)d_in[10];
    const float* enc_fcW   = (const float*)d_in[11];
    const float* enc_fcb   = (const float*)d_in[12];
    const float* attn_Wh   = (const float*)d_in[13];
    const float* attn_We   = (const float*)d_in[14];
    const float* attn_b    = (const float*)d_in[15];
    const float* attn_v    = (const float*)d_in[16];
    const float* dec_emb   = (const float*)d_in[17];
    const float* dec_Wih   = (const float*)d_in[18];
    const float* dec_Whh   = (const float*)d_in[19];
    const float* dec_bih   = (const float*)d_in[20];
    const float* dec_bhh   = (const float*)d_in[21];
    const float* fcW       = (const float*)d_in[22];
    const float* fcb       = (const float*)d_in[23];
    float* out = (float*)d_out;

    cudaFuncSetAttribute(tc_gemm_pair,
                         cudaFuncAttributeMaxDynamicSharedMemorySize, PAIR_SMEM);
    cudaFuncSetAttribute(tc_gemm_f32,
                         cudaFuncAttributeMaxDynamicSharedMemorySize, F32_SMEM);

    float* encInF   = symf(g_encInF);
    float* encInB   = symf(g_encInB);
    float* decEmbW  = symf(g_decEmbW);
    float* decEmbFc = symf(g_decEmbFc);
    float* hFa = symf(g_hFa); float* hFb = symf(g_hFb);
    float* hBa = symf(g_hBa); float* hBb = symf(g_hBb);
    float* gh1 = symf(g_gh1); float* gh2 = symf(g_gh2);
    float* encBse  = symf(g_encBse);
    float* encProj = symf(g_encProj);
    float* hcat    = symf(g_hcat);
    float* dhA = symf(g_dhA); float* dhB = symf(g_dhB);
    float* hWhGh = symf(g_hWhGh);
    float* bcomb = symf(g_bcomb);

    bf16* hFaHi = symb(g_hFaHi); bf16* hFaLo = symb(g_hFaLo);
    bf16* hFbHi = symb(g_hFbHi); bf16* hFbLo = symb(g_hFbLo);
    bf16* hBaHi = symb(g_hBaHi); bf16* hBaLo = symb(g_hBaLo);
    bf16* hBbHi = symb(g_hBbHi); bf16* hBbLo = symb(g_hBbLo);
    bf16* dhAHi = symb(g_dhAHi); bf16* dhALo = symb(g_dhALo);
    bf16* dhBHi = symb(g_dhBHi); bf16* dhBLo = symb(g_dhBLo);
    bf16* WfHi = symb(g_WfHi); bf16* WfLo = symb(g_WfLo);
    bf16* WbHi = symb(g_WbHi); bf16* WbLo = symb(g_WbLo);
    bf16* WcombHi = symb(g_WcombHi); bf16* WcombLo = symb(g_WcombLo);
    bf16* Wih2Hi = symb(g_Wih2Hi); bf16* Wih2Lo = symb(g_Wih2Lo);
    bf16* fcW1Hi = symb(g_fcW1Hi); bf16* fcW1Lo = symb(g_fcW1Lo);
    bf16* catHi = symb(g_catHi); bf16* catLo = symb(g_catLo);

    // zero initial hidden states (fp32 + pairs; bf16 zero = 0x0000) and out slice 0
    zero_kernel<<<(BB * HH + 255) / 256, 256>>>(hFa, BB * HH);
    zero_kernel<<<(BB * HH + 255) / 256, 256>>>(hBa, BB * HH);
    zero_kernel<<<(BB * HH / 2 + 255) / 256, 256>>>((float*)hFaHi, BB * HH / 2);
    zero_kernel<<<(BB * HH / 2 + 255) / 256, 256>>>((float*)hFaLo, BB * HH / 2);
    zero_kernel<<<(BB * HH / 2 + 255) / 256, 256>>>((float*)hBaHi, BB * HH / 2);
    zero_kernel<<<(BB * HH / 2 + 255) / 256, 256>>>((float*)hBaLo, BB * HH / 2);
    zero_kernel<<<(BB * VOUT + 255) / 256, 256>>>(out, BB * VOUT);

    // tables + weight prep
    {
        int total = VIN * G3 * 2 + VOUT * G3 + VOUT * VOUT;
        tables_kernel<<<(total + 255) / 256, 256>>>(
            enc_emb, dec_emb,
            enc_Wih_f, enc_bih_f, enc_Wih_b, enc_bih_b,
            dec_Wih, dec_bih, fcW + 768 * VOUT, fcb,
            encInF, encInB, decEmbW, decEmbFc);
    }
    comb_split_kernel<<<(HH * 1024 + 255) / 256, 256>>>(attn_Wh, dec_Whh, dec_bhh,
                                                        WcombHi, WcombLo, bcomb);
    wsplit_kernel<<<(HH * G3 + 255) / 256, 256>>>(enc_Whh_f, HH, G3, WfHi, WfLo);
    wsplit_kernel<<<(HH * G3 + 255) / 256, 256>>>(enc_Whh_b, HH, G3, WbHi, WbLo);
    wsplit_kernel<<<(512 * G3 + 255) / 256, 256>>>(dec_Wih + EE * G3, 512, G3, Wih2Hi, Wih2Lo);
    wsplit_kernel<<<(G3 * VOUT + 255) / 256, 256>>>(fcW, G3, VOUT, fcW1Hi, fcW1Lo);

    // ---------------- encoder: bidirectional GRU, both directions batched ----------------
    float* hf_in = hFa; float* hf_out = hFb;
    float* hb_in = hBa; float* hb_out = hBb;
    bf16 *hfiH = hFaHi, *hfiL = hFaLo, *hfoH = hFbHi, *hfoL = hFbLo;
    bf16 *hbiH = hBaHi, *hbiL = hBaLo, *hboH = hBbHi, *hboL = hBbLo;
    for (int s = 0; s < SS; s++) {
        pgemm(hfiH, hfiL, hbiH, hbiL, HH,
              WfHi, WfLo, WbHi, WbLo, HH,
              gh1, gh2, G3, BB, G3, HH,
              enc_bhh_f, enc_bhh_b, nullptr, nullptr, 0, 2);
        enc_gate_kernel<<<2 * BB, 256>>>(encInF, encInB, src, s,
                                         gh1, gh2, hf_in, hb_in, hf_out, hb_out,
                                         hfoH, hfoL, hboH, hboL, encBse);
        { float* t0 = hf_in; hf_in = hf_out; hf_out = t0; }
        { float* t1 = hb_in; hb_in = hb_out; hb_out = t1; }
        { bf16* t; t = hfiH; hfiH = hfoH; hfoH = t; t = hfiL; hfiL = hfoL; hfoL = t; }
        { bf16* t; t = hbiH; hbiH = hboH; hboH = t; t = hbiL; hbiL = hboL; hboL = t; }
    }
    // hidden = tanh([hf, hb] @ enc_fcW + enc_fcb) -> dhA (+pairs)
    concat2_kernel<<<(BB * 512 + 255) / 256, 256>>>(hf_in, HH, hb_in, HH, hcat, BB);
    {
        dim3 grid(HH / 64, BB / 128);
        tc_gemm_f32<<<grid, 256, F32_SMEM>>>(hcat, 512, enc_fcW, HH, dhA, HH,
                                             512, enc_fcb, 1);
    }
    split_kernel<<<(BB * HH + 255) / 256, 256>>>(dhA, dhAHi, dhALo, BB * HH);

    // enc_proj = enc_bse @ attn_We : (B*S, 512) x (512, 256)
    {
        dim3 grid(HH / 64, BB * SS / 128);
        tc_gemm_f32<<<grid, 256, F32_SMEM>>>(encBse, 512, attn_We, HH, encProj, HH,
                                             512, nullptr, 0);
    }

    // ---------------- decoder ----------------
    float* h_in = dhA; float* h_out = dhB;
    bf16 *hiH = dhAHi, *hiL = dhALo, *hoH = dhBHi, *hoL = dhBLo;
    for (int t = 0; t < TT - 1; t++) {
        bf16* slotHi = catHi + (size_t)t * BB * G3;
        bf16* slotLo = catLo + (size_t)t * BB * G3;
        // [hWh | gh] = h_in @ [attn_Wh | dec_Whh] + [0 | dec_bhh]
        pgemm(hiH, hiL, nullptr, nullptr, HH,
              WcombHi, WcombLo, nullptr, nullptr, HH,
              hWhGh, nullptr, 1024, BB, 1024, HH,
              bcomb, nullptr, nullptr, nullptr, 0, 1);
        // attention -> weighted pairs in slot cols [256:768)
        attn_kernel<<<BB, 256>>>(hWhGh, encProj, encBse, attn_b, attn_v, slotHi, slotLo);
        // gi = weighted @ dec_Wih[300:812] + decEmbW[trg[t]]
        pgemm(slotHi + 256, slotLo + 256, nullptr, nullptr, G3,
              Wih2Hi, Wih2Lo, nullptr, nullptr, 512,
              gh1, nullptr, G3, BB, G3, 512,
              nullptr, nullptr, decEmbW, trg + t * BB, G3, 1);
        // gates -> h_out (fp32+pairs) and slot cols [0:256) pairs
        gru_gate_kernel<<<BB * HH / 256, 256>>>(gh1, G3, hWhGh + 256, 1024,
                                                h_in, h_out, hoH, hoL, slotHi, slotLo);
        { float* t2 = h_in; h_in = h_out; h_out = t2; }
        { bf16* t3; t3 = hiH; hiH = hoH; hoH = t3; t3 = hiL; hiL = hoL; hoL = t3; }
    }

    // All logits at once: (24*2048, 768) @ fcW[0:768] + decEmbFc[trg[:-1]]
    pgemm(catHi, catLo, nullptr, nullptr, G3,
          fcW1Hi, fcW1Lo, nullptr, nullptr, G3,
          out + (size_t)BB * VOUT, nullptr, VOUT, (TT - 1) * BB, VOUT, G3,
          nullptr, nullptr, decEmbFc, trg, VOUT, 1);
}